// round 6
// baseline (speedup 1.0000x reference)
#include <cuda_runtime.h>
#include <cuda_bf16.h>
#include <mma.h>
#include <cstdint>

using namespace nvcuda;

// Problem constants
#define BATCH   4
#define SQ      4096
#define SK      1024
#define D_EMB   1024
#define D_CRUZ  768
#define N_HEADS 16
#define D_HEAD  64

// Scratch (static device allocations — allowed)
__device__ float g_q[BATCH * SQ * D_EMB];     // 64 MB
__device__ float g_k[BATCH * SK * D_EMB];     // 16 MB
__device__ float g_v[BATCH * SK * D_EMB];     // 16 MB
__device__ float g_attn[BATCH * SQ * D_EMB];  // 64 MB

// ---------------------------------------------------------------------------
// helpers
// ---------------------------------------------------------------------------
template <class Frag>
__device__ __forceinline__ void frag_to_tf32(Frag& f) {
#pragma unroll
    for (int i = 0; i < f.num_elements; i++) f.x[i] = wmma::__float_to_tf32(f.x[i]);
}

__device__ __forceinline__ void cp_async16(float* dst_smem, const float* src) {
    unsigned int d = (unsigned int)__cvta_generic_to_shared(dst_smem);
    asm volatile("cp.async.ca.shared.global [%0], [%1], 16;\n" :: "r"(d), "l"(src));
}
__device__ __forceinline__ void cp_commit() {
    asm volatile("cp.async.commit_group;\n");
}
template <int N>
__device__ __forceinline__ void cp_wait() {
    asm volatile("cp.async.wait_group %0;\n" :: "n"(N));
}

// ---------------------------------------------------------------------------
// GEMM v2 (unchanged from round 5): 128x128x32 tf32, 2-stage cp.async
// ---------------------------------------------------------------------------
#define BM 128
#define BN 128
#define BK 32
#define LDA 40
#define LDB 136
#define A_STG (BM * LDA)
#define B_STG (BK * LDB)
#define STG_FLOATS (A_STG + B_STG)
#define GEMM_SMEM_FLOATS (2 * STG_FLOATS)
#define GEMM_SMEM_BYTES  (GEMM_SMEM_FLOATS * 4)

__global__ __launch_bounds__(256)
void gemm_bias_tf32_v2(const float* __restrict__ A, const float* __restrict__ W,
                       const float* __restrict__ bias, float* __restrict__ C,
                       int M, int N, int K) {
    extern __shared__ float sm[];
    const int tid  = threadIdx.x;
    const int warp = tid >> 5;
    const int wm   = warp >> 1;
    const int wn   = warp & 1;
    const int bm   = blockIdx.y * BM;
    const int bn   = blockIdx.x * BN;

    wmma::fragment<wmma::accumulator, 16, 16, 8, float> acc[2][4];
#pragma unroll
    for (int r = 0; r < 2; r++)
#pragma unroll
        for (int c = 0; c < 4; c++) wmma::fill_fragment(acc[r][c], 0.0f);

    auto issue = [&](int kt, int buf) {
        float* As = sm + buf * STG_FLOATS;
        float* Bs = As + A_STG;
        const float* Ag = A + (size_t)bm * K + kt * BK;
        const float* Wg = W + (size_t)(kt * BK) * N + bn;
#pragma unroll
        for (int i = 0; i < 4; i++) {
            int p   = tid + i * 256;
            int row = p >> 3;
            int col = (p & 7) * 4;
            cp_async16(&As[row * LDA + col], Ag + (size_t)row * K + col);
        }
#pragma unroll
        for (int i = 0; i < 4; i++) {
            int p   = tid + i * 256;
            int row = p >> 5;
            int col = (p & 31) * 4;
            cp_async16(&Bs[row * LDB + col], Wg + (size_t)row * N + col);
        }
    };

    const int NK = K / BK;
    issue(0, 0);
    cp_commit();

    for (int kt = 0; kt < NK; kt++) {
        if (kt + 1 < NK) {
            issue(kt + 1, (kt + 1) & 1);
            cp_commit();
            cp_wait<1>();
        } else {
            cp_wait<0>();
        }
        __syncthreads();

        float* As = sm + (kt & 1) * STG_FLOATS;
        float* Bs = As + A_STG;
#pragma unroll
        for (int kk = 0; kk < BK; kk += 8) {
            wmma::fragment<wmma::matrix_a, 16, 16, 8, wmma::precision::tf32, wmma::row_major> a[2];
#pragma unroll
            for (int r = 0; r < 2; r++) {
                wmma::load_matrix_sync(a[r], &As[(wm * 32 + r * 16) * LDA + kk], LDA);
                frag_to_tf32(a[r]);
            }
#pragma unroll
            for (int c = 0; c < 4; c++) {
                wmma::fragment<wmma::matrix_b, 16, 16, 8, wmma::precision::tf32, wmma::row_major> b;
                wmma::load_matrix_sync(b, &Bs[kk * LDB + wn * 64 + c * 16], LDB);
                frag_to_tf32(b);
#pragma unroll
                for (int r = 0; r < 2; r++)
                    wmma::mma_sync(acc[r][c], a[r], b, acc[r][c]);
            }
        }
        __syncthreads();
    }

    float* Cs = sm;
#pragma unroll
    for (int r = 0; r < 2; r++)
#pragma unroll
        for (int c = 0; c < 4; c++)
            wmma::store_matrix_sync(&Cs[(wm * 32 + r * 16) * LDB + wn * 64 + c * 16],
                                    acc[r][c], LDB, wmma::mem_row_major);
    __syncthreads();

#pragma unroll
    for (int i = 0; i < 16; i++) {
        int p   = tid + i * 256;
        int row = p >> 5;
        int col = (p & 31) * 4;
        float4 v = *reinterpret_cast<float4*>(&Cs[row * LDB + col]);
        float4 bb = *reinterpret_cast<const float4*>(&bias[bn + col]);
        v.x += bb.x; v.y += bb.y; v.z += bb.z; v.w += bb.w;
        *reinterpret_cast<float4*>(&C[(size_t)(bm + row) * N + bn + col]) = v;
    }
}

// ---------------------------------------------------------------------------
// Flash attention v3: 128-row Q tile, 512 threads (16 warps in 8x2),
// cp.async double-buffered K/V (64-row tiles), Q pre-scaled by 1/8.
// Per K-tile: S=Q@K^T (tf32 wmma), block softmax, O=O*alpha (+P@V into O).
// smem ~186KB -> 1 CTA/SM (16 warps resident).
// ---------------------------------------------------------------------------
#define QT 128
#define KT 64
#define LDS_ 72
#define QS_FLOATS  (QT * LDS_)          // 9216
#define KVS_FLOATS (KT * LDS_)          // 4608 per buffer
#define ATTN_SMEM_FLOATS (QS_FLOATS * 3 + KVS_FLOATS * 4 + 512)
#define ATTN_SMEM_BYTES  (ATTN_SMEM_FLOATS * 4)   // ~186 KB

__global__ __launch_bounds__(512)
void attn_flash_tf32_v3(const float* __restrict__ qg, const float* __restrict__ kg,
                        const float* __restrict__ vg, float* __restrict__ og) {
    extern __shared__ float smem[];
    float* Qs   = smem;                          // 128 x 72
    float* Ps   = Qs + QS_FLOATS;                // 128 x 72
    float* Os   = Ps + QS_FLOATS;                // 128 x 72
    float* Kbuf = Os + QS_FLOATS;                // 2 x 64 x 72
    float* Vbuf = Kbuf + 2 * KVS_FLOATS;         // 2 x 64 x 72
    float* mrow = Vbuf + 2 * KVS_FLOATS;         // 128
    float* lrow = mrow + 128;                    // 128
    float* arow = lrow + 128;                    // 128

    const int tid  = threadIdx.x;
    const int warp = tid >> 5;
    const int wm   = warp >> 1;                  // 0..7 -> 16-row band
    const int wn   = warp & 1;                   // 0..1 -> 32-col band
    const int q0 = blockIdx.x * QT;
    const int h  = blockIdx.y;
    const int b  = blockIdx.z;
    const float scale = 0.125f;

    // Load Q tile (128x64), pre-scaled; init state
#pragma unroll
    for (int i = 0; i < 4; i++) {
        int p   = tid + i * 512;                 // 2048 float4 slots
        int row = p >> 4;
        int col = (p & 15) * 4;
        float4 v = *reinterpret_cast<const float4*>(
            &qg[((size_t)(b * SQ + q0 + row)) * D_EMB + h * D_HEAD + col]);
        v.x *= scale; v.y *= scale; v.z *= scale; v.w *= scale;
        *reinterpret_cast<float4*>(&Qs[row * LDS_ + col]) = v;
    }
    for (int i = tid; i < QS_FLOATS; i += 512) Os[i] = 0.0f;
    if (tid < 128) { mrow[tid] = -1e30f; lrow[tid] = 0.0f; arow[tid] = 1.0f; }

    auto issue_kv = [&](int kt, int buf) {
        const int k0 = kt * KT;
        float* Ks = Kbuf + buf * KVS_FLOATS;
        float* Vs = Vbuf + buf * KVS_FLOATS;
#pragma unroll
        for (int i = 0; i < 2; i++) {            // 1024 float4 per tensor
            int p   = tid + i * 512;
            int row = p >> 4;
            int col = (p & 15) * 4;
            size_t gidx = ((size_t)(b * SK + k0 + row)) * D_EMB + h * D_HEAD + col;
            cp_async16(&Ks[row * LDS_ + col], &kg[gidx]);
            cp_async16(&Vs[row * LDS_ + col], &vg[gidx]);
        }
    };

    issue_kv(0, 0);
    cp_commit();

    const int NKT = SK / KT;                     // 16
    for (int kt = 0; kt < NKT; kt++) {
        if (kt + 1 < NKT) {
            issue_kv(kt + 1, (kt + 1) & 1);
            cp_commit();
            cp_wait<1>();
        } else {
            cp_wait<0>();
        }
        __syncthreads();

        float* Ks = Kbuf + (kt & 1) * KVS_FLOATS;
        float* Vs = Vbuf + (kt & 1) * KVS_FLOATS;

        // S = Q @ K^T  (each warp: 16 rows x 32 cols)
        {
            wmma::fragment<wmma::accumulator, 16, 16, 8, float> sacc[2];
            wmma::fill_fragment(sacc[0], 0.0f);
            wmma::fill_fragment(sacc[1], 0.0f);
#pragma unroll
            for (int kk = 0; kk < 64; kk += 8) {
                wmma::fragment<wmma::matrix_a, 16, 16, 8, wmma::precision::tf32, wmma::row_major> a;
                wmma::load_matrix_sync(a, &Qs[wm * 16 * LDS_ + kk], LDS_);
                frag_to_tf32(a);
#pragma unroll
                for (int f = 0; f < 2; f++) {
                    wmma::fragment<wmma::matrix_b, 16, 16, 8, wmma::precision::tf32, wmma::col_major> kb;
                    wmma::load_matrix_sync(kb, &Ks[(wn * 32 + f * 16) * LDS_ + kk], LDS_);
                    frag_to_tf32(kb);
                    wmma::mma_sync(sacc[f], a, kb, sacc[f]);
                }
            }
#pragma unroll
            for (int f = 0; f < 2; f++)
                wmma::store_matrix_sync(&Ps[wm * 16 * LDS_ + wn * 32 + f * 16], sacc[f],
                                        LDS_, wmma::mem_row_major);
        }
        __syncthreads();

        // Online softmax: 4 threads per row (512 threads / 128 rows), 16 cols each
        {
            const int row = tid >> 2;
            const int sub = tid & 3;
            const int c0  = sub * 16;
            float mx = -1e30f;
#pragma unroll
            for (int c = 0; c < 16; c++) mx = fmaxf(mx, Ps[row * LDS_ + c0 + c]);
            mx = fmaxf(mx, __shfl_xor_sync(0xffffffffu, mx, 1));
            mx = fmaxf(mx, __shfl_xor_sync(0xffffffffu, mx, 2));
            const float mold = mrow[row];
            const float mnew = fmaxf(mold, mx);
            float sum = 0.0f;
#pragma unroll
            for (int c = 0; c < 16; c++) {
                float p = __expf(Ps[row * LDS_ + c0 + c] - mnew);
                Ps[row * LDS_ + c0 + c] = p;
                sum += p;
            }
            sum += __shfl_xor_sync(0xffffffffu, sum, 1);
            sum += __shfl_xor_sync(0xffffffffu, sum, 2);
            const float alpha = __expf(mold - mnew);
            if (sub == 0) {
                mrow[row] = mnew;
                lrow[row] = lrow[row] * alpha + sum;
                arow[row] = alpha;
            }
        }
        __syncthreads();

        // Rescale O, then PV accumulates into O tile via accumulator load
#pragma unroll
        for (int i = 0; i < 16; i++) {           // 128*64 / 512 = 16
            int p   = tid + i * 512;
            int row = p >> 6;
            int col = p & 63;
            Os[row * LDS_ + col] *= arow[row];
        }
        __syncthreads();

        {
            wmma::fragment<wmma::accumulator, 16, 16, 8, float> pacc[2];
#pragma unroll
            for (int f = 0; f < 2; f++)
                wmma::load_matrix_sync(pacc[f], &Os[wm * 16 * LDS_ + wn * 32 + f * 16],
                                       LDS_, wmma::mem_row_major);
#pragma unroll
            for (int kk = 0; kk < 64; kk += 8) {
                wmma::fragment<wmma::matrix_a, 16, 16, 8, wmma::precision::tf32, wmma::row_major> a;
                wmma::load_matrix_sync(a, &Ps[wm * 16 * LDS_ + kk], LDS_);
                frag_to_tf32(a);
#pragma unroll
                for (int f = 0; f < 2; f++) {
                    wmma::fragment<wmma::matrix_b, 16, 16, 8, wmma::precision::tf32, wmma::row_major> vb;
                    wmma::load_matrix_sync(vb, &Vs[kk * LDS_ + wn * 32 + f * 16], LDS_);
                    frag_to_tf32(vb);
                    wmma::mma_sync(pacc[f], a, vb, pacc[f]);
                }
            }
#pragma unroll
            for (int f = 0; f < 2; f++)
                wmma::store_matrix_sync(&Os[wm * 16 * LDS_ + wn * 32 + f * 16], pacc[f],
                                        LDS_, wmma::mem_row_major);
        }
        __syncthreads();
    }

    // Final: write O / l
#pragma unroll
    for (int i = 0; i < 16; i++) {
        int p   = tid + i * 512;
        int row = p >> 6;
        int col = p & 63;
        og[((size_t)(b * SQ + q0 + row)) * D_EMB + h * D_HEAD + col] =
            Os[row * LDS_ + col] / lrow[row];
    }
}

// ---------------------------------------------------------------------------
// Launcher
// ---------------------------------------------------------------------------
extern "C" void kernel_launch(void* const* d_in, const int* in_sizes, int n_in,
                              void* d_out, int out_size) {
    const float* x  = (const float*)d_in[0];
    const float* y  = (const float*)d_in[1];
    const float* Wq = (const float*)d_in[2];
    const float* bq = (const float*)d_in[3];
    const float* Wk = (const float*)d_in[4];
    const float* bk = (const float*)d_in[5];
    const float* Wv = (const float*)d_in[6];
    const float* bv = (const float*)d_in[7];
    const float* Wo = (const float*)d_in[8];
    const float* bo = (const float*)d_in[9];
    float* out = (float*)d_out;

    float *gq, *gk, *gv, *ga;
    cudaGetSymbolAddress((void**)&gq, g_q);
    cudaGetSymbolAddress((void**)&gk, g_k);
    cudaGetSymbolAddress((void**)&gv, g_v);
    cudaGetSymbolAddress((void**)&ga, g_attn);

    cudaFuncSetAttribute(gemm_bias_tf32_v2,
                         cudaFuncAttributeMaxDynamicSharedMemorySize, GEMM_SMEM_BYTES);
    cudaFuncSetAttribute(attn_flash_tf32_v3,
                         cudaFuncAttributeMaxDynamicSharedMemorySize, ATTN_SMEM_BYTES);

    // Projections
    gemm_bias_tf32_v2<<<dim3(D_EMB / BN, (BATCH * SQ) / BM), 256, GEMM_SMEM_BYTES>>>(
        x, Wq, bq, gq, BATCH * SQ, D_EMB, D_EMB);
    gemm_bias_tf32_v2<<<dim3(D_EMB / BN, (BATCH * SK) / BM), 256, GEMM_SMEM_BYTES>>>(
        y, Wk, bk, gk, BATCH * SK, D_EMB, D_CRUZ);
    gemm_bias_tf32_v2<<<dim3(D_EMB / BN, (BATCH * SK) / BM), 256, GEMM_SMEM_BYTES>>>(
        y, Wv, bv, gv, BATCH * SK, D_EMB, D_CRUZ);

    // Attention (128-row Q tiles)
    attn_flash_tf32_v3<<<dim3(SQ / QT, N_HEADS, BATCH), 512, ATTN_SMEM_BYTES>>>(gq, gk, gv, ga);

    // Output projection
    gemm_bias_tf32_v2<<<dim3(D_EMB / BN, (BATCH * SQ) / BM), 256, GEMM_SMEM_BYTES>>>(
        ga, Wo, bo, out, BATCH * SQ, D_EMB, D_EMB);
}

// round 9
// speedup vs baseline: 1.6002x; 1.6002x over previous
#include <cuda_runtime.h>
#include <cuda_bf16.h>
#include <mma.h>
#include <cstdint>

using namespace nvcuda;

// Problem constants
#define BATCH   4
#define SQ      4096
#define SK      1024
#define D_EMB   1024
#define D_CRUZ  768
#define N_HEADS 16
#define D_HEAD  64

// Scratch (static device allocations — allowed)
__device__ float g_q[BATCH * SQ * D_EMB];     // 64 MB
__device__ float g_k[BATCH * SK * D_EMB];     // 16 MB
__device__ float g_v[BATCH * SK * D_EMB];     // 16 MB
__device__ float g_attn[BATCH * SQ * D_EMB];  // 64 MB

// ---------------------------------------------------------------------------
// helpers
// ---------------------------------------------------------------------------
template <class Frag>
__device__ __forceinline__ void frag_to_tf32(Frag& f) {
#pragma unroll
    for (int i = 0; i < f.num_elements; i++) f.x[i] = wmma::__float_to_tf32(f.x[i]);
}

__device__ __forceinline__ void cp_async16(float* dst_smem, const float* src) {
    unsigned int d = (unsigned int)__cvta_generic_to_shared(dst_smem);
    asm volatile("cp.async.ca.shared.global [%0], [%1], 16;\n" :: "r"(d), "l"(src));
}
__device__ __forceinline__ void cp_commit() {
    asm volatile("cp.async.commit_group;\n");
}
template <int N>
__device__ __forceinline__ void cp_wait() {
    asm volatile("cp.async.wait_group %0;\n" :: "n"(N));
}

__device__ __forceinline__ uint32_t f2tf(float f) {
    uint32_t u;
    asm("cvt.rna.tf32.f32 %0, %1;" : "=r"(u) : "f"(f));
    return u;
}

// mma.m16n8k8 tf32: D(16x8,f32) += A(16x8,row) * B(8x8,col)
// Verified layouts (gid=lane>>2, tig=lane&3):
//   A: a0=(gid,tig) a1=(gid+8,tig) a2=(gid,tig+4) a3=(gid+8,tig+4)
//   B: b0=(k=tig,n=gid) b1=(k=tig+4,n=gid)
//   C: c0=(gid,2tig) c1=(gid,2tig+1) c2=(gid+8,2tig) c3=(gid+8,2tig+1)
__device__ __forceinline__ void mma_tf32(float* d, const uint32_t* a,
                                         uint32_t b0, uint32_t b1) {
    asm volatile(
        "mma.sync.aligned.m16n8k8.row.col.f32.tf32.tf32.f32 "
        "{%0,%1,%2,%3}, {%4,%5,%6,%7}, {%8,%9}, {%0,%1,%2,%3};"
        : "+f"(d[0]), "+f"(d[1]), "+f"(d[2]), "+f"(d[3])
        : "r"(a[0]), "r"(a[1]), "r"(a[2]), "r"(a[3]), "r"(b0), "r"(b1));
}

// ---------------------------------------------------------------------------
// GEMM v2 (unchanged): 128x128x32 tf32, 2-stage cp.async
// ---------------------------------------------------------------------------
#define BM 128
#define BN 128
#define BK 32
#define LDA 40
#define LDB 136
#define A_STG (BM * LDA)
#define B_STG (BK * LDB)
#define STG_FLOATS (A_STG + B_STG)
#define GEMM_SMEM_BYTES (2 * STG_FLOATS * 4)

__global__ __launch_bounds__(256)
void gemm_bias_tf32_v2(const float* __restrict__ A, const float* __restrict__ W,
                       const float* __restrict__ bias, float* __restrict__ C,
                       int M, int N, int K) {
    extern __shared__ float sm[];
    const int tid  = threadIdx.x;
    const int warp = tid >> 5;
    const int wm   = warp >> 1;
    const int wn   = warp & 1;
    const int bm   = blockIdx.y * BM;
    const int bn   = blockIdx.x * BN;

    wmma::fragment<wmma::accumulator, 16, 16, 8, float> acc[2][4];
#pragma unroll
    for (int r = 0; r < 2; r++)
#pragma unroll
        for (int c = 0; c < 4; c++) wmma::fill_fragment(acc[r][c], 0.0f);

    auto issue = [&](int kt, int buf) {
        float* As = sm + buf * STG_FLOATS;
        float* Bs = As + A_STG;
        const float* Ag = A + (size_t)bm * K + kt * BK;
        const float* Wg = W + (size_t)(kt * BK) * N + bn;
#pragma unroll
        for (int i = 0; i < 4; i++) {
            int p   = tid + i * 256;
            int row = p >> 3;
            int col = (p & 7) * 4;
            cp_async16(&As[row * LDA + col], Ag + (size_t)row * K + col);
        }
#pragma unroll
        for (int i = 0; i < 4; i++) {
            int p   = tid + i * 256;
            int row = p >> 5;
            int col = (p & 31) * 4;
            cp_async16(&Bs[row * LDB + col], Wg + (size_t)row * N + col);
        }
    };

    const int NK = K / BK;
    issue(0, 0);
    cp_commit();

    for (int kt = 0; kt < NK; kt++) {
        if (kt + 1 < NK) {
            issue(kt + 1, (kt + 1) & 1);
            cp_commit();
            cp_wait<1>();
        } else {
            cp_wait<0>();
        }
        __syncthreads();

        float* As = sm + (kt & 1) * STG_FLOATS;
        float* Bs = As + A_STG;
#pragma unroll
        for (int kk = 0; kk < BK; kk += 8) {
            wmma::fragment<wmma::matrix_a, 16, 16, 8, wmma::precision::tf32, wmma::row_major> a[2];
#pragma unroll
            for (int r = 0; r < 2; r++) {
                wmma::load_matrix_sync(a[r], &As[(wm * 32 + r * 16) * LDA + kk], LDA);
                frag_to_tf32(a[r]);
            }
#pragma unroll
            for (int c = 0; c < 4; c++) {
                wmma::fragment<wmma::matrix_b, 16, 16, 8, wmma::precision::tf32, wmma::row_major> b;
                wmma::load_matrix_sync(b, &Bs[kk * LDB + wn * 64 + c * 16], LDB);
                frag_to_tf32(b);
#pragma unroll
                for (int r = 0; r < 2; r++)
                    wmma::mma_sync(acc[r][c], a[r], b, acc[r][c]);
            }
        }
        __syncthreads();
    }

    float* Cs = sm;
#pragma unroll
    for (int r = 0; r < 2; r++)
#pragma unroll
        for (int c = 0; c < 4; c++)
            wmma::store_matrix_sync(&Cs[(wm * 32 + r * 16) * LDB + wn * 64 + c * 16],
                                    acc[r][c], LDB, wmma::mem_row_major);
    __syncthreads();

#pragma unroll
    for (int i = 0; i < 16; i++) {
        int p   = tid + i * 256;
        int row = p >> 5;
        int col = (p & 31) * 4;
        float4 v = *reinterpret_cast<float4*>(&Cs[row * LDB + col]);
        float4 bb = *reinterpret_cast<const float4*>(&bias[bn + col]);
        v.x += bb.x; v.y += bb.y; v.z += bb.z; v.w += bb.w;
        *reinterpret_cast<float4*>(&C[(size_t)(bm + row) * N + bn + col]) = v;
    }
}

// ---------------------------------------------------------------------------
// Flash attention v6 (FA2, register-resident): 128-row Q tile, 256 threads.
// Fragment layouts per verified m16n8k8 tf32 spec; C->A permutation for P.
// FIX vs round 7: Q staging loads all 2048 float4 (8 iterations, not 4).
// ---------------------------------------------------------------------------
#define QT 128
#define KT 64
#define LDQ 76
#define LDK 76
#define LDV 72
#define QS_FL (QT * LDQ)                        // 9728
#define KS_FL (KT * LDK)                        // 4864
#define VS_FL (KT * LDV)                        // 4608
#define ATTN_SMEM_FLOATS (QS_FL + 2 * KS_FL + 2 * VS_FL)
#define ATTN_SMEM_BYTES  (ATTN_SMEM_FLOATS * 4) // ~114.7 KB

__global__ __launch_bounds__(256)
void attn_fa2_tf32(const float* __restrict__ qg, const float* __restrict__ kg,
                   const float* __restrict__ vg, float* __restrict__ og) {
    extern __shared__ float smem[];
    float* Qs = smem;                           // 128 x 76
    float* Kb = Qs + QS_FL;                     // 2 x 64 x 76
    float* Vb = Kb + 2 * KS_FL;                 // 2 x 64 x 72

    const int tid  = threadIdx.x;
    const int warp = tid >> 5;
    const int lane = tid & 31;
    const int gid  = lane >> 2;                 // 0..7
    const int tig  = lane & 3;                  // 0..3
    const int q0 = blockIdx.x * QT;
    const int h  = blockIdx.y;
    const int b  = blockIdx.z;
    const float scale = 0.125f;

    // Stage Q tile (128x64 = 2048 float4), pre-scaled  [FIXED: 8 iterations]
#pragma unroll
    for (int i = 0; i < 8; i++) {
        int p   = tid + i * 256;                // 0..2047
        int row = p >> 4;                       // 0..127
        int col = (p & 15) * 4;
        float4 v = *reinterpret_cast<const float4*>(
            &qg[((size_t)(b * SQ + q0 + row)) * D_EMB + h * D_HEAD + col]);
        v.x *= scale; v.y *= scale; v.z *= scale; v.w *= scale;
        *reinterpret_cast<float4*>(&Qs[row * LDQ + col]) = v;
    }
    __syncthreads();

    // Q A-fragments: a0=(r0,tig) a1=(r0+8,tig) a2=(r0,tig+4) a3=(r0+8,tig+4)
    const int r0 = warp * 16 + gid;
    uint32_t qf[8][4];
#pragma unroll
    for (int kc = 0; kc < 8; kc++) {
        qf[kc][0] = f2tf(Qs[r0 * LDQ + kc * 8 + tig]);
        qf[kc][1] = f2tf(Qs[(r0 + 8) * LDQ + kc * 8 + tig]);
        qf[kc][2] = f2tf(Qs[r0 * LDQ + kc * 8 + tig + 4]);
        qf[kc][3] = f2tf(Qs[(r0 + 8) * LDQ + kc * 8 + tig + 4]);
    }

    float o[8][4];
#pragma unroll
    for (int j = 0; j < 8; j++)
#pragma unroll
        for (int e = 0; e < 4; e++) o[j][e] = 0.0f;
    float m0 = -1e30f, m1 = -1e30f, l0 = 0.0f, l1 = 0.0f;

    auto issue_kv = [&](int kt, int buf) {
        const int k0 = kt * KT;
        float* Ks = Kb + buf * KS_FL;
        float* Vs = Vb + buf * VS_FL;
#pragma unroll
        for (int i = 0; i < 4; i++) {           // 64x64 = 1024 float4 per tensor
            int p   = tid + i * 256;
            int row = p >> 4;
            int col = (p & 15) * 4;
            size_t g = ((size_t)(b * SK + k0 + row)) * D_EMB + h * D_HEAD + col;
            cp_async16(&Ks[row * LDK + col], &kg[g]);
            cp_async16(&Vs[row * LDV + col], &vg[g]);
        }
    };

    issue_kv(0, 0);
    cp_commit();

    const int NKT = SK / KT;                    // 16
    for (int kt = 0; kt < NKT; kt++) {
        if (kt + 1 < NKT) {
            issue_kv(kt + 1, (kt + 1) & 1);
            cp_commit();
            cp_wait<1>();
        } else {
            cp_wait<0>();
        }
        __syncthreads();

        const float* Ks = Kb + (kt & 1) * KS_FL;
        const float* Vs = Vb + (kt & 1) * VS_FL;

        // ---- S = Q @ K^T : s[j] covers keys j*8..j*8+7 ----
        float s[8][4];
#pragma unroll
        for (int j = 0; j < 8; j++)
#pragma unroll
            for (int e = 0; e < 4; e++) s[j][e] = 0.0f;

#pragma unroll
        for (int kc = 0; kc < 8; kc++) {
#pragma unroll
            for (int j = 0; j < 8; j++) {
                // B: b0=(k=tig,n=gid) -> K[key j*8+gid][dim kc*8+tig]; b1: dim+4
                uint32_t b0 = f2tf(Ks[(j * 8 + gid) * LDK + kc * 8 + tig]);
                uint32_t b1 = f2tf(Ks[(j * 8 + gid) * LDK + kc * 8 + tig + 4]);
                mma_tf32(s[j], qf[kc], b0, b1);
            }
        }

        // ---- online softmax (C layout: [0,1]=row r0 cols 2tig,2tig+1; [2,3]=row r0+8) ----
        float mx0 = -1e30f, mx1 = -1e30f;
#pragma unroll
        for (int j = 0; j < 8; j++) {
            mx0 = fmaxf(mx0, fmaxf(s[j][0], s[j][1]));
            mx1 = fmaxf(mx1, fmaxf(s[j][2], s[j][3]));
        }
        mx0 = fmaxf(mx0, __shfl_xor_sync(0xffffffffu, mx0, 1));
        mx0 = fmaxf(mx0, __shfl_xor_sync(0xffffffffu, mx0, 2));
        mx1 = fmaxf(mx1, __shfl_xor_sync(0xffffffffu, mx1, 1));
        mx1 = fmaxf(mx1, __shfl_xor_sync(0xffffffffu, mx1, 2));

        const float mn0 = fmaxf(m0, mx0);
        const float mn1 = fmaxf(m1, mx1);
        float sum0 = 0.0f, sum1 = 0.0f;
#pragma unroll
        for (int j = 0; j < 8; j++) {
            s[j][0] = __expf(s[j][0] - mn0);
            s[j][1] = __expf(s[j][1] - mn0);
            s[j][2] = __expf(s[j][2] - mn1);
            s[j][3] = __expf(s[j][3] - mn1);
            sum0 += s[j][0] + s[j][1];
            sum1 += s[j][2] + s[j][3];
        }
        sum0 += __shfl_xor_sync(0xffffffffu, sum0, 1);
        sum0 += __shfl_xor_sync(0xffffffffu, sum0, 2);
        sum1 += __shfl_xor_sync(0xffffffffu, sum1, 1);
        sum1 += __shfl_xor_sync(0xffffffffu, sum1, 2);

        const float al0 = __expf(m0 - mn0);
        const float al1 = __expf(m1 - mn1);
        l0 = l0 * al0 + sum0;
        l1 = l1 * al1 + sum1;
        m0 = mn0; m1 = mn1;

#pragma unroll
        for (int j = 0; j < 8; j++) {
            o[j][0] *= al0; o[j][1] *= al0;
            o[j][2] *= al1; o[j][3] *= al1;
        }

        // ---- permute P: C layout (cols 2tig,2tig+1) -> A layout (k=tig,tig+4) ----
        uint32_t pa[8][4];
        const int srcA = (lane & ~3) | (tig >> 1);        // holds col = tig (c0/c1)
        const int srcB = (lane & ~3) | (2 + (tig >> 1));  // holds col = tig+4
        const bool oddc = (tig & 1);
#pragma unroll
        for (int j = 0; j < 8; j++) {
            float x0 = __shfl_sync(0xffffffffu, s[j][0], srcA);
            float x1 = __shfl_sync(0xffffffffu, s[j][1], srcA);
            float y0 = __shfl_sync(0xffffffffu, s[j][0], srcB);
            float y1 = __shfl_sync(0xffffffffu, s[j][1], srcB);
            float z0 = __shfl_sync(0xffffffffu, s[j][2], srcA);
            float z1 = __shfl_sync(0xffffffffu, s[j][3], srcA);
            float w0 = __shfl_sync(0xffffffffu, s[j][2], srcB);
            float w1 = __shfl_sync(0xffffffffu, s[j][3], srcB);
            pa[j][0] = f2tf(oddc ? x1 : x0);   // a0 = P[r0][tig]
            pa[j][1] = f2tf(oddc ? z1 : z0);   // a1 = P[r0+8][tig]
            pa[j][2] = f2tf(oddc ? y1 : y0);   // a2 = P[r0][tig+4]
            pa[j][3] = f2tf(oddc ? w1 : w0);   // a3 = P[r0+8][tig+4]
        }

        // ---- O += P @ V : pa[kc] = keys kc*8..+7; j = 8-dim chunk ----
#pragma unroll
        for (int kc = 0; kc < 8; kc++) {
#pragma unroll
            for (int j = 0; j < 8; j++) {
                // B: b0 = V[key kc*8+tig][dim j*8+gid]; b1 = key kc*8+tig+4
                uint32_t b0 = f2tf(Vs[(kc * 8 + tig) * LDV + j * 8 + gid]);
                uint32_t b1 = f2tf(Vs[(kc * 8 + tig + 4) * LDV + j * 8 + gid]);
                mma_tf32(o[j], pa[kc], b0, b1);
            }
        }
        __syncthreads();   // all reads of this K/V buffer done before reuse
    }

    // ---- epilogue: O / l (C layout: cols 2tig,2tig+1 per dim chunk) ----
    const float inv0 = 1.0f / l0;
    const float inv1 = 1.0f / l1;
    const size_t rowbase0 = ((size_t)(b * SQ + q0 + r0)) * D_EMB + h * D_HEAD;
    const size_t rowbase1 = rowbase0 + 8 * D_EMB;
#pragma unroll
    for (int j = 0; j < 8; j++) {
        int col = j * 8 + 2 * tig;
        *reinterpret_cast<float2*>(&og[rowbase0 + col]) =
            make_float2(o[j][0] * inv0, o[j][1] * inv0);
        *reinterpret_cast<float2*>(&og[rowbase1 + col]) =
            make_float2(o[j][2] * inv1, o[j][3] * inv1);
    }
}

// ---------------------------------------------------------------------------
// Launcher
// ---------------------------------------------------------------------------
extern "C" void kernel_launch(void* const* d_in, const int* in_sizes, int n_in,
                              void* d_out, int out_size) {
    const float* x  = (const float*)d_in[0];
    const float* y  = (const float*)d_in[1];
    const float* Wq = (const float*)d_in[2];
    const float* bq = (const float*)d_in[3];
    const float* Wk = (const float*)d_in[4];
    const float* bk = (const float*)d_in[5];
    const float* Wv = (const float*)d_in[6];
    const float* bv = (const float*)d_in[7];
    const float* Wo = (const float*)d_in[8];
    const float* bo = (const float*)d_in[9];
    float* out = (float*)d_out;

    float *gq, *gk, *gv, *ga;
    cudaGetSymbolAddress((void**)&gq, g_q);
    cudaGetSymbolAddress((void**)&gk, g_k);
    cudaGetSymbolAddress((void**)&gv, g_v);
    cudaGetSymbolAddress((void**)&ga, g_attn);

    cudaFuncSetAttribute(gemm_bias_tf32_v2,
                         cudaFuncAttributeMaxDynamicSharedMemorySize, GEMM_SMEM_BYTES);
    cudaFuncSetAttribute(attn_fa2_tf32,
                         cudaFuncAttributeMaxDynamicSharedMemorySize, ATTN_SMEM_BYTES);

    // Projections
    gemm_bias_tf32_v2<<<dim3(D_EMB / BN, (BATCH * SQ) / BM), 256, GEMM_SMEM_BYTES>>>(
        x, Wq, bq, gq, BATCH * SQ, D_EMB, D_EMB);
    gemm_bias_tf32_v2<<<dim3(D_EMB / BN, (BATCH * SK) / BM), 256, GEMM_SMEM_BYTES>>>(
        y, Wk, bk, gk, BATCH * SK, D_EMB, D_CRUZ);
    gemm_bias_tf32_v2<<<dim3(D_EMB / BN, (BATCH * SK) / BM), 256, GEMM_SMEM_BYTES>>>(
        y, Wv, bv, gv, BATCH * SK, D_EMB, D_CRUZ);

    // Attention (register-resident FA2)
    attn_fa2_tf32<<<dim3(SQ / QT, N_HEADS, BATCH), 256, ATTN_SMEM_BYTES>>>(gq, gk, gv, ga);

    // Output projection
    gemm_bias_tf32_v2<<<dim3(D_EMB / BN, (BATCH * SQ) / BM), 256, GEMM_SMEM_BYTES>>>(
        ga, Wo, bo, out, BATCH * SQ, D_EMB, D_EMB);
}

// round 10
// speedup vs baseline: 1.7956x; 1.1221x over previous
#include <cuda_runtime.h>
#include <cuda_bf16.h>
#include <mma.h>
#include <cstdint>

using namespace nvcuda;

// Problem constants
#define BATCH   4
#define SQ      4096
#define SK      1024
#define D_EMB   1024
#define D_CRUZ  768
#define N_HEADS 16
#define D_HEAD  64

// Scratch (static device allocations — allowed)
__device__ float g_q[BATCH * SQ * D_EMB];     // 64 MB
__device__ float g_k[BATCH * SK * D_EMB];     // 16 MB
__device__ float g_v[BATCH * SK * D_EMB];     // 16 MB
__device__ float g_attn[BATCH * SQ * D_EMB];  // 64 MB
// tf32-pre-rounded inputs/weights
__device__ float g_xr[BATCH * SQ * D_EMB];    // 64 MB
__device__ float g_yr[BATCH * SK * D_CRUZ];   // 12 MB
__device__ float g_wq[D_EMB * D_EMB];         // 4 MB
__device__ float g_wk[D_CRUZ * D_EMB];        // 3 MB
__device__ float g_wv[D_CRUZ * D_EMB];        // 3 MB
__device__ float g_wo[D_EMB * D_EMB];         // 4 MB

// ---------------------------------------------------------------------------
// helpers
// ---------------------------------------------------------------------------
__device__ __forceinline__ void cp_async16(float* dst_smem, const float* src) {
    unsigned int d = (unsigned int)__cvta_generic_to_shared(dst_smem);
    asm volatile("cp.async.ca.shared.global [%0], [%1], 16;\n" :: "r"(d), "l"(src));
}
__device__ __forceinline__ void cp_commit() {
    asm volatile("cp.async.commit_group;\n");
}
template <int N>
__device__ __forceinline__ void cp_wait() {
    asm volatile("cp.async.wait_group %0;\n" :: "n"(N));
}

__device__ __forceinline__ uint32_t f2tf(float f) {
    uint32_t u;
    asm("cvt.rna.tf32.f32 %0, %1;" : "=r"(u) : "f"(f));
    return u;
}
__device__ __forceinline__ float roundtf(float f) {
    return __uint_as_float(f2tf(f));
}

// mma.m16n8k8 tf32 (verified layouts; gid=lane>>2, tig=lane&3):
//   A: a0=(gid,tig) a1=(gid+8,tig) a2=(gid,tig+4) a3=(gid+8,tig+4)
//   B: b0=(k=tig,n=gid) b1=(k=tig+4,n=gid)
//   C: c0=(gid,2tig) c1=(gid,2tig+1) c2=(gid+8,2tig) c3=(gid+8,2tig+1)
__device__ __forceinline__ void mma_tf32(float* d, const uint32_t* a,
                                         uint32_t b0, uint32_t b1) {
    asm volatile(
        "mma.sync.aligned.m16n8k8.row.col.f32.tf32.tf32.f32 "
        "{%0,%1,%2,%3}, {%4,%5,%6,%7}, {%8,%9}, {%0,%1,%2,%3};"
        : "+f"(d[0]), "+f"(d[1]), "+f"(d[2]), "+f"(d[3])
        : "r"(a[0]), "r"(a[1]), "r"(a[2]), "r"(a[3]), "r"(b0), "r"(b1));
}

// ---------------------------------------------------------------------------
// Pre-round: convert x, y, and the four weight matrices to tf32-rounded fp32.
// Segment offsets in float4 units.
// ---------------------------------------------------------------------------
#define SEG_X  4194304                          // BATCH*SQ*D_EMB/4
#define SEG_Y  (SEG_X + 786432)                 // + BATCH*SK*D_CRUZ/4
#define SEG_WQ (SEG_Y + 262144)                 // + D_EMB*D_EMB/4
#define SEG_WK (SEG_WQ + 196608)                // + D_CRUZ*D_EMB/4
#define SEG_WV (SEG_WK + 196608)
#define SEG_WO (SEG_WV + 262144)                // total float4 count

__global__ __launch_bounds__(256)
void preround_all(const float4* __restrict__ x, const float4* __restrict__ y,
                  const float4* __restrict__ wq, const float4* __restrict__ wk,
                  const float4* __restrict__ wv, const float4* __restrict__ wo,
                  float4* __restrict__ xr, float4* __restrict__ yr,
                  float4* __restrict__ wqr, float4* __restrict__ wkr,
                  float4* __restrict__ wvr, float4* __restrict__ wor) {
    for (long i = (long)blockIdx.x * blockDim.x + threadIdx.x; i < SEG_WO;
         i += (long)gridDim.x * blockDim.x) {
        const float4* src; float4* dst; long o;
        if (i < SEG_X)       { src = x;  dst = xr;  o = i; }
        else if (i < SEG_Y)  { src = y;  dst = yr;  o = i - SEG_X; }
        else if (i < SEG_WQ) { src = wq; dst = wqr; o = i - SEG_Y; }
        else if (i < SEG_WK) { src = wk; dst = wkr; o = i - SEG_WQ; }
        else if (i < SEG_WV) { src = wv; dst = wvr; o = i - SEG_WK; }
        else                 { src = wo; dst = wor; o = i - SEG_WV; }
        float4 v = src[o];
        v.x = roundtf(v.x); v.y = roundtf(v.y);
        v.z = roundtf(v.z); v.w = roundtf(v.w);
        dst[o] = v;
    }
}

// ---------------------------------------------------------------------------
// GEMM v3: 128x128x32 tf32, 2-stage cp.async. Inputs pre-rounded to tf32,
// so no per-load conversion. ROUND_OUT rounds the result to tf32 on store
// (used for q/k/v/attn intermediates consumed as tf32 downstream).
// ---------------------------------------------------------------------------
#define BM 128
#define BN 128
#define BK 32
#define LDA 40
#define LDB 136
#define A_STG (BM * LDA)
#define B_STG (BK * LDB)
#define STG_FLOATS (A_STG + B_STG)
#define GEMM_SMEM_BYTES (2 * STG_FLOATS * 4)

template <bool ROUND_OUT>
__global__ __launch_bounds__(256)
void gemm_bias_tf32_v3(const float* __restrict__ A, const float* __restrict__ W,
                       const float* __restrict__ bias, float* __restrict__ C,
                       int M, int N, int K) {
    extern __shared__ float sm[];
    const int tid  = threadIdx.x;
    const int warp = tid >> 5;
    const int wm   = warp >> 1;
    const int wn   = warp & 1;
    const int bm   = blockIdx.y * BM;
    const int bn   = blockIdx.x * BN;

    wmma::fragment<wmma::accumulator, 16, 16, 8, float> acc[2][4];
#pragma unroll
    for (int r = 0; r < 2; r++)
#pragma unroll
        for (int c = 0; c < 4; c++) wmma::fill_fragment(acc[r][c], 0.0f);

    auto issue = [&](int kt, int buf) {
        float* As = sm + buf * STG_FLOATS;
        float* Bs = As + A_STG;
        const float* Ag = A + (size_t)bm * K + kt * BK;
        const float* Wg = W + (size_t)(kt * BK) * N + bn;
#pragma unroll
        for (int i = 0; i < 4; i++) {
            int p   = tid + i * 256;
            int row = p >> 3;
            int col = (p & 7) * 4;
            cp_async16(&As[row * LDA + col], Ag + (size_t)row * K + col);
        }
#pragma unroll
        for (int i = 0; i < 4; i++) {
            int p   = tid + i * 256;
            int row = p >> 5;
            int col = (p & 31) * 4;
            cp_async16(&Bs[row * LDB + col], Wg + (size_t)row * N + col);
        }
    };

    const int NK = K / BK;
    issue(0, 0);
    cp_commit();

    for (int kt = 0; kt < NK; kt++) {
        if (kt + 1 < NK) {
            issue(kt + 1, (kt + 1) & 1);
            cp_commit();
            cp_wait<1>();
        } else {
            cp_wait<0>();
        }
        __syncthreads();

        float* As = sm + (kt & 1) * STG_FLOATS;
        float* Bs = As + A_STG;
#pragma unroll
        for (int kk = 0; kk < BK; kk += 8) {
            wmma::fragment<wmma::matrix_a, 16, 16, 8, wmma::precision::tf32, wmma::row_major> a[2];
#pragma unroll
            for (int r = 0; r < 2; r++)
                wmma::load_matrix_sync(a[r], &As[(wm * 32 + r * 16) * LDA + kk], LDA);
#pragma unroll
            for (int c = 0; c < 4; c++) {
                wmma::fragment<wmma::matrix_b, 16, 16, 8, wmma::precision::tf32, wmma::row_major> b;
                wmma::load_matrix_sync(b, &Bs[kk * LDB + wn * 64 + c * 16], LDB);
#pragma unroll
                for (int r = 0; r < 2; r++)
                    wmma::mma_sync(acc[r][c], a[r], b, acc[r][c]);
            }
        }
        __syncthreads();
    }

    float* Cs = sm;
#pragma unroll
    for (int r = 0; r < 2; r++)
#pragma unroll
        for (int c = 0; c < 4; c++)
            wmma::store_matrix_sync(&Cs[(wm * 32 + r * 16) * LDB + wn * 64 + c * 16],
                                    acc[r][c], LDB, wmma::mem_row_major);
    __syncthreads();

#pragma unroll
    for (int i = 0; i < 16; i++) {
        int p   = tid + i * 256;
        int row = p >> 5;
        int col = (p & 31) * 4;
        float4 v = *reinterpret_cast<float4*>(&Cs[row * LDB + col]);
        float4 bb = *reinterpret_cast<const float4*>(&bias[bn + col]);
        v.x += bb.x; v.y += bb.y; v.z += bb.z; v.w += bb.w;
        if (ROUND_OUT) {
            v.x = roundtf(v.x); v.y = roundtf(v.y);
            v.z = roundtf(v.z); v.w = roundtf(v.w);
        }
        *reinterpret_cast<float4*>(&C[(size_t)(bm + row) * N + bn + col]) = v;
    }
}

// ---------------------------------------------------------------------------
// Flash attention v7 (FA2, register-resident): q/k/v arrive tf32-pre-rounded,
// so Q/K/V fragment loads are raw bit reinterprets (no cvt). P still cvt'd.
// Output written tf32-rounded (feeds O-projection as A operand).
// ---------------------------------------------------------------------------
#define QT 128
#define KT 64
#define LDQ 76
#define LDK 76
#define LDV 72
#define QS_FL (QT * LDQ)
#define KS_FL (KT * LDK)
#define VS_FL (KT * LDV)
#define ATTN_SMEM_FLOATS (QS_FL + 2 * KS_FL + 2 * VS_FL)
#define ATTN_SMEM_BYTES  (ATTN_SMEM_FLOATS * 4) // ~114.7 KB

__global__ __launch_bounds__(256)
void attn_fa2_tf32(const float* __restrict__ qg, const float* __restrict__ kg,
                   const float* __restrict__ vg, float* __restrict__ og) {
    extern __shared__ float smem[];
    float* Qs = smem;                           // 128 x 76
    float* Kb = Qs + QS_FL;                     // 2 x 64 x 76
    float* Vb = Kb + 2 * KS_FL;                 // 2 x 64 x 72

    const int tid  = threadIdx.x;
    const int warp = tid >> 5;
    const int lane = tid & 31;
    const int gid  = lane >> 2;
    const int tig  = lane & 3;
    const int q0 = blockIdx.x * QT;
    const int h  = blockIdx.y;
    const int b  = blockIdx.z;
    const float scale = 0.125f;                 // power of 2: preserves tf32 rounding

    // Stage Q tile (128x64 = 2048 float4), pre-scaled
#pragma unroll
    for (int i = 0; i < 8; i++) {
        int p   = tid + i * 256;
        int row = p >> 4;
        int col = (p & 15) * 4;
        float4 v = *reinterpret_cast<const float4*>(
            &qg[((size_t)(b * SQ + q0 + row)) * D_EMB + h * D_HEAD + col]);
        v.x *= scale; v.y *= scale; v.z *= scale; v.w *= scale;
        *reinterpret_cast<float4*>(&Qs[row * LDQ + col]) = v;
    }
    __syncthreads();

    // Q A-fragments (raw bits — already tf32)
    const int r0 = warp * 16 + gid;
    uint32_t qf[8][4];
#pragma unroll
    for (int kc = 0; kc < 8; kc++) {
        qf[kc][0] = __float_as_uint(Qs[r0 * LDQ + kc * 8 + tig]);
        qf[kc][1] = __float_as_uint(Qs[(r0 + 8) * LDQ + kc * 8 + tig]);
        qf[kc][2] = __float_as_uint(Qs[r0 * LDQ + kc * 8 + tig + 4]);
        qf[kc][3] = __float_as_uint(Qs[(r0 + 8) * LDQ + kc * 8 + tig + 4]);
    }

    float o[8][4];
#pragma unroll
    for (int j = 0; j < 8; j++)
#pragma unroll
        for (int e = 0; e < 4; e++) o[j][e] = 0.0f;
    float m0 = -1e30f, m1 = -1e30f, l0 = 0.0f, l1 = 0.0f;

    auto issue_kv = [&](int kt, int buf) {
        const int k0 = kt * KT;
        float* Ks = Kb + buf * KS_FL;
        float* Vs = Vb + buf * VS_FL;
#pragma unroll
        for (int i = 0; i < 4; i++) {
            int p   = tid + i * 256;
            int row = p >> 4;
            int col = (p & 15) * 4;
            size_t g = ((size_t)(b * SK + k0 + row)) * D_EMB + h * D_HEAD + col;
            cp_async16(&Ks[row * LDK + col], &kg[g]);
            cp_async16(&Vs[row * LDV + col], &vg[g]);
        }
    };

    issue_kv(0, 0);
    cp_commit();

    const int NKT = SK / KT;
    for (int kt = 0; kt < NKT; kt++) {
        if (kt + 1 < NKT) {
            issue_kv(kt + 1, (kt + 1) & 1);
            cp_commit();
            cp_wait<1>();
        } else {
            cp_wait<0>();
        }
        __syncthreads();

        const float* Ks = Kb + (kt & 1) * KS_FL;
        const float* Vs = Vb + (kt & 1) * VS_FL;

        // ---- S = Q @ K^T ----
        float s[8][4];
#pragma unroll
        for (int j = 0; j < 8; j++)
#pragma unroll
            for (int e = 0; e < 4; e++) s[j][e] = 0.0f;

#pragma unroll
        for (int kc = 0; kc < 8; kc++) {
#pragma unroll
            for (int j = 0; j < 8; j++) {
                uint32_t b0 = __float_as_uint(Ks[(j * 8 + gid) * LDK + kc * 8 + tig]);
                uint32_t b1 = __float_as_uint(Ks[(j * 8 + gid) * LDK + kc * 8 + tig + 4]);
                mma_tf32(s[j], qf[kc], b0, b1);
            }
        }

        // ---- online softmax ----
        float mx0 = -1e30f, mx1 = -1e30f;
#pragma unroll
        for (int j = 0; j < 8; j++) {
            mx0 = fmaxf(mx0, fmaxf(s[j][0], s[j][1]));
            mx1 = fmaxf(mx1, fmaxf(s[j][2], s[j][3]));
        }
        mx0 = fmaxf(mx0, __shfl_xor_sync(0xffffffffu, mx0, 1));
        mx0 = fmaxf(mx0, __shfl_xor_sync(0xffffffffu, mx0, 2));
        mx1 = fmaxf(mx1, __shfl_xor_sync(0xffffffffu, mx1, 1));
        mx1 = fmaxf(mx1, __shfl_xor_sync(0xffffffffu, mx1, 2));

        const float mn0 = fmaxf(m0, mx0);
        const float mn1 = fmaxf(m1, mx1);
        float sum0 = 0.0f, sum1 = 0.0f;
#pragma unroll
        for (int j = 0; j < 8; j++) {
            s[j][0] = __expf(s[j][0] - mn0);
            s[j][1] = __expf(s[j][1] - mn0);
            s[j][2] = __expf(s[j][2] - mn1);
            s[j][3] = __expf(s[j][3] - mn1);
            sum0 += s[j][0] + s[j][1];
            sum1 += s[j][2] + s[j][3];
        }
        sum0 += __shfl_xor_sync(0xffffffffu, sum0, 1);
        sum0 += __shfl_xor_sync(0xffffffffu, sum0, 2);
        sum1 += __shfl_xor_sync(0xffffffffu, sum1, 1);
        sum1 += __shfl_xor_sync(0xffffffffu, sum1, 2);

        const float al0 = __expf(m0 - mn0);
        const float al1 = __expf(m1 - mn1);
        l0 = l0 * al0 + sum0;
        l1 = l1 * al1 + sum1;
        m0 = mn0; m1 = mn1;

#pragma unroll
        for (int j = 0; j < 8; j++) {
            o[j][0] *= al0; o[j][1] *= al0;
            o[j][2] *= al1; o[j][3] *= al1;
        }

        // ---- permute P: C layout -> A layout (shuffles), cvt once ----
        uint32_t pa[8][4];
        const int srcA = (lane & ~3) | (tig >> 1);
        const int srcB = (lane & ~3) | (2 + (tig >> 1));
        const bool oddc = (tig & 1);
#pragma unroll
        for (int j = 0; j < 8; j++) {
            float x0 = __shfl_sync(0xffffffffu, s[j][0], srcA);
            float x1 = __shfl_sync(0xffffffffu, s[j][1], srcA);
            float y0 = __shfl_sync(0xffffffffu, s[j][0], srcB);
            float y1 = __shfl_sync(0xffffffffu, s[j][1], srcB);
            float z0 = __shfl_sync(0xffffffffu, s[j][2], srcA);
            float z1 = __shfl_sync(0xffffffffu, s[j][3], srcA);
            float w0 = __shfl_sync(0xffffffffu, s[j][2], srcB);
            float w1 = __shfl_sync(0xffffffffu, s[j][3], srcB);
            pa[j][0] = f2tf(oddc ? x1 : x0);
            pa[j][1] = f2tf(oddc ? z1 : z0);
            pa[j][2] = f2tf(oddc ? y1 : y0);
            pa[j][3] = f2tf(oddc ? w1 : w0);
        }

        // ---- O += P @ V ----
#pragma unroll
        for (int kc = 0; kc < 8; kc++) {
#pragma unroll
            for (int j = 0; j < 8; j++) {
                uint32_t b0 = __float_as_uint(Vs[(kc * 8 + tig) * LDV + j * 8 + gid]);
                uint32_t b1 = __float_as_uint(Vs[(kc * 8 + tig + 4) * LDV + j * 8 + gid]);
                mma_tf32(o[j], pa[kc], b0, b1);
            }
        }
        __syncthreads();
    }

    // ---- epilogue: (O / l) rounded to tf32 for the O-projection ----
    const float inv0 = 1.0f / l0;
    const float inv1 = 1.0f / l1;
    const size_t rowbase0 = ((size_t)(b * SQ + q0 + r0)) * D_EMB + h * D_HEAD;
    const size_t rowbase1 = rowbase0 + 8 * D_EMB;
#pragma unroll
    for (int j = 0; j < 8; j++) {
        int col = j * 8 + 2 * tig;
        *reinterpret_cast<float2*>(&og[rowbase0 + col]) =
            make_float2(roundtf(o[j][0] * inv0), roundtf(o[j][1] * inv0));
        *reinterpret_cast<float2*>(&og[rowbase1 + col]) =
            make_float2(roundtf(o[j][2] * inv1), roundtf(o[j][3] * inv1));
    }
}

// ---------------------------------------------------------------------------
// Launcher
// ---------------------------------------------------------------------------
extern "C" void kernel_launch(void* const* d_in, const int* in_sizes, int n_in,
                              void* d_out, int out_size) {
    const float* x  = (const float*)d_in[0];
    const float* y  = (const float*)d_in[1];
    const float* Wq = (const float*)d_in[2];
    const float* bq = (const float*)d_in[3];
    const float* Wk = (const float*)d_in[4];
    const float* bk = (const float*)d_in[5];
    const float* Wv = (const float*)d_in[6];
    const float* bv = (const float*)d_in[7];
    const float* Wo = (const float*)d_in[8];
    const float* bo = (const float*)d_in[9];
    float* out = (float*)d_out;

    float *gq, *gk, *gv, *ga, *xr, *yr, *wqr, *wkr, *wvr, *wor;
    cudaGetSymbolAddress((void**)&gq, g_q);
    cudaGetSymbolAddress((void**)&gk, g_k);
    cudaGetSymbolAddress((void**)&gv, g_v);
    cudaGetSymbolAddress((void**)&ga, g_attn);
    cudaGetSymbolAddress((void**)&xr, g_xr);
    cudaGetSymbolAddress((void**)&yr, g_yr);
    cudaGetSymbolAddress((void**)&wqr, g_wq);
    cudaGetSymbolAddress((void**)&wkr, g_wk);
    cudaGetSymbolAddress((void**)&wvr, g_wv);
    cudaGetSymbolAddress((void**)&wor, g_wo);

    cudaFuncSetAttribute(gemm_bias_tf32_v3<true>,
                         cudaFuncAttributeMaxDynamicSharedMemorySize, GEMM_SMEM_BYTES);
    cudaFuncSetAttribute(gemm_bias_tf32_v3<false>,
                         cudaFuncAttributeMaxDynamicSharedMemorySize, GEMM_SMEM_BYTES);
    cudaFuncSetAttribute(attn_fa2_tf32,
                         cudaFuncAttributeMaxDynamicSharedMemorySize, ATTN_SMEM_BYTES);

    // Pre-round inputs + weights to tf32
    preround_all<<<2048, 256>>>((const float4*)x, (const float4*)y,
                                (const float4*)Wq, (const float4*)Wk,
                                (const float4*)Wv, (const float4*)Wo,
                                (float4*)xr, (float4*)yr, (float4*)wqr,
                                (float4*)wkr, (float4*)wvr, (float4*)wor);

    // Projections (outputs tf32-rounded: consumed as tf32 by attention)
    gemm_bias_tf32_v3<true><<<dim3(D_EMB / BN, (BATCH * SQ) / BM), 256, GEMM_SMEM_BYTES>>>(
        xr, wqr, bq, gq, BATCH * SQ, D_EMB, D_EMB);
    gemm_bias_tf32_v3<true><<<dim3(D_EMB / BN, (BATCH * SK) / BM), 256, GEMM_SMEM_BYTES>>>(
        yr, wkr, bk, gk, BATCH * SK, D_EMB, D_CRUZ);
    gemm_bias_tf32_v3<true><<<dim3(D_EMB / BN, (BATCH * SK) / BM), 256, GEMM_SMEM_BYTES>>>(
        yr, wvr, bv, gv, BATCH * SK, D_EMB, D_CRUZ);

    // Attention (register-resident FA2; output tf32-rounded)
    attn_fa2_tf32<<<dim3(SQ / QT, N_HEADS, BATCH), 256, ATTN_SMEM_BYTES>>>(gq, gk, gv, ga);

    // Output projection (full-precision fp32 output)
    gemm_bias_tf32_v3<false><<<dim3(D_EMB / BN, (BATCH * SQ) / BM), 256, GEMM_SMEM_BYTES>>>(
        ga, wor, bo, out, BATCH * SQ, D_EMB, D_EMB);
}